// round 1
// baseline (speedup 1.0000x reference)
#include <cuda_runtime.h>
#include <math.h>

#define T_STEPS 512
#define B_SZ    128
#define NI_SZ   512
#define D_SZ    512
#define G4_SZ   2048   // 4*D

// Scratch for intern = X@Wf + bf : 512 MB device global (allocation-free rule workaround)
__device__ float g_intern[(size_t)T_STEPS * B_SZ * G4_SZ];

// ---------------------------------------------------------------------------
// Phase 1: intern[M=65536][2048] = X[M][512] @ Wf[512][2048] + bf
// Classic 128x128x8 tile, 256 threads, 8x8 per thread.
// ---------------------------------------------------------------------------
__global__ __launch_bounds__(256)
void gemm_intern_kernel(const float* __restrict__ X,
                        const float* __restrict__ Wf,
                        const float* __restrict__ bf)
{
    __shared__ __align__(16) float As[8][128];
    __shared__ __align__(16) float Bs[8][128];

    const int t  = threadIdx.x;
    const int tx = t & 15;
    const int ty = t >> 4;
    const int m0 = blockIdx.y * 128;
    const int n0 = blockIdx.x * 128;

    const int arow = t >> 1, acol = (t & 1) * 4;
    const int brow = t >> 5, bcol = (t & 31) * 4;

    const float* Aptr = X  + (size_t)(m0 + arow) * NI_SZ + acol;
    const float* Bptr = Wf + (size_t)brow * G4_SZ + n0 + bcol;

    float acc[8][8];
    #pragma unroll
    for (int i = 0; i < 8; i++)
        #pragma unroll
        for (int j = 0; j < 8; j++) acc[i][j] = 0.f;

    for (int k0 = 0; k0 < NI_SZ; k0 += 8) {
        float4 av = *(const float4*)(Aptr + k0);
        float4 bv = *(const float4*)(Bptr + (size_t)k0 * G4_SZ);
        __syncthreads();
        As[acol + 0][arow] = av.x;
        As[acol + 1][arow] = av.y;
        As[acol + 2][arow] = av.z;
        As[acol + 3][arow] = av.w;
        *(float4*)&Bs[brow][bcol] = bv;
        __syncthreads();
        #pragma unroll
        for (int k = 0; k < 8; k++) {
            float a[8], b[8];
            *(float4*)(a)     = *(const float4*)&As[k][ty * 4];
            *(float4*)(a + 4) = *(const float4*)&As[k][64 + ty * 4];
            *(float4*)(b)     = *(const float4*)&Bs[k][tx * 4];
            *(float4*)(b + 4) = *(const float4*)&Bs[k][64 + tx * 4];
            #pragma unroll
            for (int i = 0; i < 8; i++)
                #pragma unroll
                for (int j = 0; j < 8; j++)
                    acc[i][j] = fmaf(a[i], b[j], acc[i][j]);
        }
    }

    float4 bias0 = *(const float4*)&bf[n0 + tx * 4];
    float4 bias1 = *(const float4*)&bf[n0 + 64 + tx * 4];
    #pragma unroll
    for (int i = 0; i < 8; i++) {
        int m = m0 + (i < 4 ? ty * 4 + i : 64 + ty * 4 + (i - 4));
        float* out = g_intern + (size_t)m * G4_SZ + n0;
        float4 v0 = make_float4(acc[i][0] + bias0.x, acc[i][1] + bias0.y,
                                acc[i][2] + bias0.z, acc[i][3] + bias0.w);
        float4 v1 = make_float4(acc[i][4] + bias1.x, acc[i][5] + bias1.y,
                                acc[i][6] + bias1.z, acc[i][7] + bias1.w);
        *(float4*)(out + tx * 4)      = v0;
        *(float4*)(out + 64 + tx * 4) = v1;
    }
}

// ---------------------------------------------------------------------------
// Phase 2: one LSTM step.
//   z[b][g*512+j] = intern[t][b][g*512+j] + sum_k h[b][k]*Wr[k][g*512+j]
// grid (32, 4): blockIdx.x -> 16 j's, blockIdx.y -> 32 b's. 256 threads.
// K split 4 ways (128 k each). Thread tile: 8 b x 4 gates x 1 j.
// Gate columns co-located per thread => fused activation epilogue.
// ---------------------------------------------------------------------------
#define KC 16   // k-chunk per split per stage

__global__ __launch_bounds__(256)
void lstm_step_kernel(int tstep,
                      const float* __restrict__ h_prev,
                      const float* __restrict__ c_prev,
                      const float* __restrict__ i_t,
                      const float* __restrict__ Wr,
                      float* __restrict__ Y_t,
                      float* __restrict__ C_t,
                      float* __restrict__ d_fin)
{
    // smem: staging [h: 4*16*36 | w: 4*16*68] then reused as reduction buf [4][64][32]
    __shared__ __align__(16) float smem[8192];
    float* sh_h = smem;              // [ks][kk][36]  (b-major rows, padded 36)
    float* sh_w = smem + 4 * KC * 36; // [ks][kk][68]  (col = jl*4 + gate, padded 68)

    const float* intern_t = g_intern + (size_t)tstep * B_SZ * G4_SZ;

    const int t    = threadIdx.x;
    const int ks   = t >> 6;        // k-split quarter
    const int slot = t & 63;
    const int tj   = slot & 15;     // j within tile
    const int bg   = slot >> 4;     // b-group of 8
    const int j0   = blockIdx.x * 16;
    const int bm0  = blockIdx.y * 32;

    float4 acc[8];
    #pragma unroll
    for (int i = 0; i < 8; i++) acc[i] = make_float4(0.f, 0.f, 0.f, 0.f);

    for (int ci = 0; ci < 128 / KC; ci++) {
        __syncthreads();
        // ---- stage h: 4 splits x 16 k x 32 b = 512 float4-loads total
        #pragma unroll
        for (int u = 0; u < 2; u++) {
            int f4  = t + u * 256;
            int lks = f4 >> 7;
            int r   = f4 & 127;
            int b   = r >> 2;
            int kq  = r & 3;
            float4 v = *(const float4*)(h_prev + (size_t)(bm0 + b) * D_SZ
                                        + lks * 128 + ci * KC + kq * 4);
            float* dst = sh_h + lks * (KC * 36) + (kq * 4) * 36 + b;
            dst[0] = v.x; dst[36] = v.y; dst[72] = v.z; dst[108] = v.w;
        }
        // ---- stage w: 4 splits x 16 k x 64 cols = 1024 float4-loads total
        #pragma unroll
        for (int u = 0; u < 4; u++) {
            int f4  = t + u * 256;
            int lks = f4 >> 8;
            int r   = f4 & 255;
            int kk  = r >> 4;
            int g   = (r >> 2) & 3;
            int jq  = r & 3;
            float4 v = *(const float4*)(Wr + (size_t)(lks * 128 + ci * KC + kk) * G4_SZ
                                        + g * D_SZ + j0 + jq * 4);
            float* dst = sh_w + lks * (KC * 68) + kk * 68 + (jq * 4) * 4 + g;
            dst[0] = v.x; dst[4] = v.y; dst[8] = v.z; dst[12] = v.w;
        }
        __syncthreads();

        const float* hbase = sh_h + ks * (KC * 36);
        const float* wbase = sh_w + ks * (KC * 68);
        #pragma unroll
        for (int kk = 0; kk < KC; kk++) {
            float4 w4 = *(const float4*)(wbase + kk * 68 + tj * 4);
            float4 ha = *(const float4*)(hbase + kk * 36 + bg * 8);
            float4 hb = *(const float4*)(hbase + kk * 36 + bg * 8 + 4);
            float hv[8] = {ha.x, ha.y, ha.z, ha.w, hb.x, hb.y, hb.z, hb.w};
            #pragma unroll
            for (int bb = 0; bb < 8; bb++) {
                acc[bb].x = fmaf(hv[bb], w4.x, acc[bb].x);
                acc[bb].y = fmaf(hv[bb], w4.y, acc[bb].y);
                acc[bb].z = fmaf(hv[bb], w4.z, acc[bb].z);
                acc[bb].w = fmaf(hv[bb], w4.w, acc[bb].w);
            }
        }
    }

    // ---- reduce across the 4 k-splits via smem (reuse staging buffer)
    __syncthreads();
    float* red = smem;  // [ks][slot(64)][32]
    #pragma unroll
    for (int bb = 0; bb < 8; bb++)
        *(float4*)(red + ks * 2048 + slot * 32 + bb * 4) = acc[bb];
    __syncthreads();

    // ---- fused epilogue: 2 (b,j) cells per thread, all 256 threads active
    #pragma unroll
    for (int u = 0; u < 2; u++) {
        int c       = t * 2 + u;        // 0..511 cells = 32 b x 16 j
        int b_local = c >> 4;
        int jl      = c & 15;
        int eslot   = (b_local >> 3) * 16 + jl;
        int ebb     = b_local & 7;

        const float* p = red + eslot * 32 + ebb * 4;
        float4 z0 = *(const float4*)(p);
        float4 z1 = *(const float4*)(p + 2048);
        float4 z2 = *(const float4*)(p + 4096);
        float4 z3 = *(const float4*)(p + 6144);
        float zc = z0.x + z1.x + z2.x + z3.x;
        float zi = z0.y + z1.y + z2.y + z3.y;
        float zf = z0.z + z1.z + z2.z + z3.z;
        float zo = z0.w + z1.w + z2.w + z3.w;

        int b = bm0 + b_local;
        int j = j0 + jl;
        const float* it = intern_t + (size_t)b * G4_SZ + j;
        zc += it[0];
        zi += it[512];
        zf += it[1024];
        zo += it[1536];

        float cin = tanhf(zc);
        float ig  = 1.f / (1.f + expf(-zi));
        float fg  = 1.f / (1.f + expf(-zf));
        float og  = 1.f / (1.f + expf(-zo));

        float m    = i_t[b];
        float cold = c_prev[(size_t)b * D_SZ + j];
        float cnew = m * (cold * fg + cin * ig) + (1.f - m) * cold;
        float y    = m * (og * tanhf(cnew));

        Y_t[(size_t)b * D_SZ + j] = y;
        C_t[(size_t)b * D_SZ + j] = cnew;
        if (d_fin) d_fin[(size_t)b * D_SZ + j] = cnew;
    }
}

// ---------------------------------------------------------------------------
// Launch: 1 GEMM + 512 sequential step kernels (graph-capturable, alloc-free)
// Inputs (metadata order): X, Wf, Wr, bf, i, h0, c0
// Output layout: Y[T,B,D] | C[T,B,D] | d[B,D] (d = C[T-1])
// ---------------------------------------------------------------------------
extern "C" void kernel_launch(void* const* d_in, const int* in_sizes, int n_in,
                              void* d_out, int out_size)
{
    (void)in_sizes; (void)n_in; (void)out_size;
    const float* X  = (const float*)d_in[0];
    const float* Wf = (const float*)d_in[1];
    const float* Wr = (const float*)d_in[2];
    const float* bf = (const float*)d_in[3];
    const float* iv = (const float*)d_in[4];
    const float* h0 = (const float*)d_in[5];
    const float* c0 = (const float*)d_in[6];

    float* out  = (float*)d_out;
    float* Y    = out;
    float* C    = out + (size_t)T_STEPS * B_SZ * D_SZ;
    float* dfin = C   + (size_t)T_STEPS * B_SZ * D_SZ;

    dim3 g1(G4_SZ / 128, (T_STEPS * B_SZ) / 128);  // (16, 512)
    gemm_intern_kernel<<<g1, 256>>>(X, Wf, bf);

    dim3 g2(D_SZ / 16, B_SZ / 32);                 // (32, 4)
    for (int t = 0; t < T_STEPS; t++) {
        const float* hp = t ? (const float*)(Y + (size_t)(t - 1) * B_SZ * D_SZ) : h0;
        const float* cp = t ? (const float*)(C + (size_t)(t - 1) * B_SZ * D_SZ) : c0;
        lstm_step_kernel<<<g2, 256>>>(t, hp, cp, iv + (size_t)t * B_SZ, Wr,
                                      Y + (size_t)t * B_SZ * D_SZ,
                                      C + (size_t)t * B_SZ * D_SZ,
                                      (t == T_STEPS - 1) ? dfin : nullptr);
    }
}